// round 15
// baseline (speedup 1.0000x reference)
#include <cuda_runtime.h>
#include <cuda_fp16.h>
#include <cuda_bf16.h>

// FFT-based 2x upsample, fully-real polyphase formulation (see R2/R3/R5/R12).
// R15 = R13 (best, 153.7us) + F2 occupancy fix done RIGHT this time:
//   z0[16] (32 live regs) is eliminated; the epilogue RELOADS x/M1 rows via
//   __ldcg (L2-resident — this block just read them; ldcg can't be CSE'd into
//   registers). Smem stays 64KB -> 2 CTAs/SM now fit by BOTH regs and smem.
//   (R14 parked z0 in a 3rd smem region: 96KB blocked the 2nd CTA. Reverted.)
//
// Pipeline: T1 (x -> xp[jp][i] half2, + twiddle fill)
//           F1 (col pass, 2048 blocks -> M1T, Dpart)
//           T2 (M1T -> M1, + deterministic D reduction)
//           F2 (row pass, 4096 blocks -> out rows 2i/2i+1 directly).

#define FN    4096
#define TPB   256
#define NPAIR (FN / 2)
#define SMEM_FFT (2 * FN * sizeof(float2))   // 64 KB double-buffer

__device__ __align__(16) __half2 g_xp [(size_t)NPAIR * FN];  // [jp][i]
__device__ __align__(16) __half2 g_M1T[(size_t)NPAIR * FN];  // [jp][i]
__device__ __align__(16) __half2 g_M1 [(size_t)FN * NPAIR];  // [i][jp]
__device__ float g_Dpart[NPAIR];
__device__ float g_D[1];
// twA[k] = e^{-2 pi i k/4096}, twB[k] = e^{+i pi k/4096}, k < 512
__device__ __align__(16) float2 g_twA[512];
__device__ __align__(16) float2 g_twB[512];

__device__ __forceinline__ float2 cmul(float2 a, float2 b) {
    return make_float2(fmaf(a.x, b.x, -a.y * b.y), fmaf(a.x, b.y, a.y * b.x));
}

// Packed fp32 complex add/sub (R10): one f32x2 instruction each.
__device__ __forceinline__ float2 cadd(float2 a, float2 b) {
    float2 r;
    asm("{\n\t.reg .b64 ra, rb, rc;\n\t"
        "mov.b64 ra, {%2, %3};\n\t"
        "mov.b64 rb, {%4, %5};\n\t"
        "add.rn.f32x2 rc, ra, rb;\n\t"
        "mov.b64 {%0, %1}, rc;\n\t}"
        : "=f"(r.x), "=f"(r.y)
        : "f"(a.x), "f"(a.y), "f"(b.x), "f"(b.y));
    return r;
}
__device__ __forceinline__ float2 csub(float2 a, float2 b) {
    float2 r;
    asm("{\n\t.reg .b64 ra, rb, rc;\n\t"
        "mov.b64 ra, {%2, %3};\n\t"
        "mov.b64 rb, {%4, %5};\n\t"
        "sub.rn.f32x2 rc, ra, rb;\n\t"
        "mov.b64 {%0, %1}, rc;\n\t}"
        : "=f"(r.x), "=f"(r.y)
        : "f"(a.x), "f"(a.y), "f"(b.x), "f"(b.y));
    return r;
}

// 16-point DFT as 4x4 radix-4 (see R11). FWD: W16 = e^{-2pi i/16}; INV: conj.
template <bool INV>
__device__ __forceinline__ void bfly16(const float2 x[16], float2 y[16]) {
    float2 v[16];
    #pragma unroll
    for (int j0 = 0; j0 < 4; j0++) {
        float2 p0 = x[j0], p1 = x[j0 + 4], p2 = x[j0 + 8], p3 = x[j0 + 12];
        float2 s02 = cadd(p0, p2), d02 = csub(p0, p2);
        float2 s13 = cadd(p1, p3), d13 = csub(p1, p3);
        float2 id13 = INV ? make_float2(-d13.y, d13.x) : make_float2(d13.y, -d13.x);
        v[4 * j0 + 0] = cadd(s02, s13);
        v[4 * j0 + 1] = cadd(d02, id13);
        v[4 * j0 + 2] = csub(s02, s13);
        v[4 * j0 + 3] = csub(d02, id13);
    }
    const float C1 = 0.92387953251128675613f, S1 = 0.38268343236508977173f;
    const float C2 = 0.70710678118654752440f;
    const float sg = INV ? 1.0f : -1.0f;
    const float2 W1 = make_float2(C1, sg * S1);
    const float2 W2 = make_float2(C2, sg * C2);
    const float2 W3 = make_float2(S1, sg * C1);
    const float2 W6 = make_float2(-C2, sg * C2);
    const float2 W9 = make_float2(-C1, -sg * S1);
    v[5]  = cmul(v[5],  W1);
    v[6]  = cmul(v[6],  W2);
    v[7]  = cmul(v[7],  W3);
    v[9]  = cmul(v[9],  W2);
    v[10] = INV ? make_float2(-v[10].y, v[10].x) : make_float2(v[10].y, -v[10].x);
    v[11] = cmul(v[11], W6);
    v[13] = cmul(v[13], W3);
    v[14] = cmul(v[14], W6);
    v[15] = cmul(v[15], W9);
    #pragma unroll
    for (int a0 = 0; a0 < 4; a0++) {
        float2 p0 = v[a0], p1 = v[4 + a0], p2 = v[8 + a0], p3 = v[12 + a0];
        float2 s02 = cadd(p0, p2), d02 = csub(p0, p2);
        float2 s13 = cadd(p1, p3), d13 = csub(p1, p3);
        float2 id13 = INV ? make_float2(-d13.y, d13.x) : make_float2(d13.y, -d13.x);
        y[a0]      = cadd(s02, s13);
        y[a0 + 4]  = cadd(d02, id13);
        y[a0 + 8]  = csub(s02, s13);
        y[a0 + 12] = csub(d02, id13);
    }
}

// y[k] *= w^k (k=1..15), w = base (conjugated for INV).
template <bool INV>
__device__ __forceinline__ void twapply16(float2 y[16], float2 wb) {
    float2 w1 = INV ? make_float2(wb.x, -wb.y) : wb;
    float2 w2 = cmul(w1, w1);
    float2 w3 = cmul(w2, w1);
    float2 w4 = cmul(w2, w2);
    float2 w5 = cmul(w4, w1);
    float2 w6 = cmul(w4, w2);
    float2 w7 = cmul(w4, w3);
    float2 w8 = cmul(w4, w4);
    y[1] = cmul(y[1], w1); y[2] = cmul(y[2], w2); y[3] = cmul(y[3], w3);
    y[4] = cmul(y[4], w4); y[5] = cmul(y[5], w5); y[6] = cmul(y[6], w6);
    y[7] = cmul(y[7], w7); y[8] = cmul(y[8], w8);
    w1 = cmul(w1, w8); w2 = cmul(w2, w8); w3 = cmul(w3, w8);
    w4 = cmul(w4, w8); w5 = cmul(w5, w8); w6 = cmul(w6, w8); w7 = cmul(w7, w8);
    y[9]  = cmul(y[9],  w1); y[10] = cmul(y[10], w2); y[11] = cmul(y[11], w3);
    y[12] = cmul(y[12], w4); y[13] = cmul(y[13], w5); y[14] = cmul(y[14], w6);
    y[15] = cmul(y[15], w7);
}

// S-transform (R11, unchanged): z[j] (= data[t + 256 j]) ->
// N * IDFT( DFT(.) * halfshift_w ), zny_out <- DFT[2048].
__device__ __forceinline__ void stransform16(float2 z[16], float2* buf0, float2* buf1,
                                             float2* s_zny, int t, float2* zny_out) {
    const int a0  = t >> 4;
    const int s4  = t & 15;
    const int m16 = a0 + 16 * s4;
    const int tSW = 16 * a0 + (s4 ^ a0);

    float2 y[16];
    const float2 w1b = __ldg(&g_twA[t]);
    const float2 w2b = __ldg(&g_twA[16 * s4]);
    const float2 wm  = __ldg(&g_twB[m16]);

    // ---- forward FFT ----
    bfly16<false>(z, y);
    twapply16<false>(y, w1b);
    #pragma unroll
    for (int a = 0; a < 16; a++) buf0[256 * a + tSW] = y[a];
    __syncthreads();
    #pragma unroll
    for (int q = 0; q < 16; q++) z[q] = buf0[256 * a0 + 16 * q + (s4 ^ q)];

    bfly16<false>(z, y);
    twapply16<false>(y, w2b);
    #pragma unroll
    for (int b = 0; b < 16; b++) buf1[256 * a0 + 16 * b + (s4 ^ b)] = y[b];
    __syncthreads();
    #pragma unroll
    for (int q = 0; q < 16; q++) z[q] = buf1[16 * t + (q ^ s4)];

    bfly16<false>(z, y);
    if (t == 0) *s_zny = y[8];                  // X[2048]

    // ---- half-sample-shift phase ----
    {
        const float2 EJ[16] = {
            { 1.0f, 0.0f},
            { 0.98078528040323044913f,  0.19509032201612826785f},
            { 0.92387953251128675613f,  0.38268343236508977173f},
            { 0.83146961230254523708f,  0.55557023301960222474f},
            { 0.70710678118654752440f,  0.70710678118654752440f},
            { 0.55557023301960222474f,  0.83146961230254523708f},
            { 0.38268343236508977173f,  0.92387953251128675613f},
            { 0.19509032201612826785f,  0.98078528040323044913f},
            { 0.0f, -1.0f},
            { 0.19509032201612826785f, -0.98078528040323044913f},
            { 0.38268343236508977173f, -0.92387953251128675613f},
            { 0.55557023301960222474f, -0.83146961230254523708f},
            { 0.70710678118654752440f, -0.70710678118654752440f},
            { 0.83146961230254523708f, -0.55557023301960222474f},
            { 0.92387953251128675613f, -0.38268343236508977173f},
            { 0.98078528040323044913f, -0.19509032201612826785f}};
        #pragma unroll
        for (int c = 0; c < 16; c++) y[c] = cmul(y[c], cmul(wm, EJ[c]));
    }

    // ---- inverse FFT (exact mirror) ----
    bfly16<true>(y, z);
    #pragma unroll
    for (int q = 0; q < 16; q++) buf0[16 * t + (q ^ s4)] = z[q];
    __syncthreads();
    #pragma unroll
    for (int q = 0; q < 16; q++) z[q] = buf0[256 * a0 + 16 * q + (s4 ^ q)];

    twapply16<true>(z, w2b);
    bfly16<true>(z, y);
    #pragma unroll
    for (int j = 0; j < 16; j++) buf1[256 * a0 + 16 * j + (s4 ^ j)] = y[j];
    __syncthreads();
    #pragma unroll
    for (int q = 0; q < 16; q++) y[q] = buf1[256 * q + tSW];

    twapply16<true>(y, w1b);
    bfly16<true>(y, z);                         // z[j] = N*S[t + 256 j]

    *zny_out = *s_zny;                          // >= 2 syncs after the write
}

// T1: x -> xp[jp][i] = half2(x[i][2jp], x[i][2jp+1]).
// Block (0,0) additionally fills the twiddle tables (read first by F1).
__global__ void t1_transpose(const float* __restrict__ x) {
    __shared__ float2 tile[32][33];
    int tx = threadIdx.x, ty = threadIdx.y;
    int lt = ty * 32 + tx;                      // 0..255
    if (blockIdx.x == 0 && blockIdx.y == 0) {
        #pragma unroll
        for (int h = 0; h < 2; h++) {
            int k = lt + 256 * h;
            float sn, cs;
            sincospif(-(float)k / 2048.0f, &sn, &cs);
            g_twA[k] = make_float2(cs, sn);
            sincospif((float)k / 4096.0f, &sn, &cs);
            g_twB[k] = make_float2(cs, sn);
        }
    }
    const float2* xf2 = reinterpret_cast<const float2*>(x);
    int cx = blockIdx.x * 32 + tx;      // jp
    int ry = blockIdx.y * 32 + ty;      // i
    #pragma unroll
    for (int j = 0; j < 32; j += 8)
        tile[ty + j][tx] = xf2[(size_t)(ry + j) * NPAIR + cx];
    __syncthreads();
    int ox = blockIdx.y * 32 + tx;      // i
    int oy = blockIdx.x * 32 + ty;      // jp
    #pragma unroll
    for (int j = 0; j < 32; j += 8) {
        float2 v = tile[tx][ty + j];
        g_xp[(size_t)(oy + j) * FN + ox] = __floats2half2_rn(v.x, v.y);
    }
}

// F1: column pass. Block jp transforms packed x-column pair (2jp, 2jp+1).
__global__ __launch_bounds__(TPB, 2) void f1_colpass() {
    extern __shared__ float2 dsm[];
    __shared__ float2 s_zny;
    float2* buf0 = dsm;
    float2* buf1 = dsm + FN;
    int tid = threadIdx.x;
    size_t jp = blockIdx.x;
    const __half2* xp = g_xp + jp * (size_t)FN;
    float2 z[16];
    #pragma unroll
    for (int e = 0; e < 16; e++) {
        int i = tid + e * TPB;
        z[e] = __half22float2(xp[i]);
    }
    float2 zny;
    stransform16(z, buf0, buf1, &s_zny, tid, &zny);
    if (tid == 0) g_Dpart[jp] = zny.x - zny.y;

    const float invN = 1.0f / 4096.0f;
    float sgn = (tid & 1) ? -1.0f : 1.0f;       // (-1)^i
    __half2* mt = g_M1T + jp * (size_t)FN;
    #pragma unroll
    for (int e = 0; e < 16; e++) {
        int i = tid + e * TPB;
        float Ru = (z[e].x - sgn * zny.y) * invN;
        float Rv = (z[e].y + sgn * zny.x) * invN;
        mt[i] = __floats2half2_rn(Ru, Rv);
    }
}

// T2: transpose M1T -> M1. Block (0,0) additionally reduces Dpart -> D.
__global__ void t2_transpose() {
    __shared__ __half2 tile[32][33];
    __shared__ float sh[256];
    int tx = threadIdx.x, ty = threadIdx.y;
    int lt = ty * 32 + tx;                      // 0..255
    if (blockIdx.x == 0 && blockIdx.y == 0) {
        float s = 0.0f;
        #pragma unroll
        for (int h = 0; h < 8; h++) s += g_Dpart[lt + 256 * h];
        sh[lt] = s;
        __syncthreads();
        for (int o = 128; o > 0; o >>= 1) {
            if (lt < o) sh[lt] += sh[lt + o];
            __syncthreads();
        }
        if (lt == 0) g_D[0] = sh[0];
    }
    int cx = blockIdx.x * 32 + tx;      // i
    int ry = blockIdx.y * 32 + ty;      // jp
    #pragma unroll
    for (int j = 0; j < 32; j += 8)
        tile[ty + j][tx] = g_M1T[(size_t)(ry + j) * FN + cx];
    __syncthreads();
    int ox = blockIdx.y * 32 + tx;      // jp
    int oy = blockIdx.x * 32 + ty;      // i
    #pragma unroll
    for (int j = 0; j < 32; j += 8)
        g_M1[(size_t)(oy + j) * NPAIR + ox] = tile[tx][ty + j];
}

// F2: row pass. No z0 registers: the epilogue reloads x/M1 via __ldcg
// (L2-resident; cannot be CSE'd into registers). 64KB smem, 2 CTAs/SM.
__global__ __launch_bounds__(TPB, 2) void f2_rowpass(const float* __restrict__ x,
                                                     float* __restrict__ out) {
    extern __shared__ float2 dsm[];
    __shared__ float2 s_zny;
    float2* buf0 = dsm;
    float2* buf1 = dsm + FN;
    int tid = threadIdx.x;
    size_t i = blockIdx.x;
    const float* xr = x + i * (size_t)FN;
    const __half2* mr = g_M1 + i * (size_t)NPAIR;
    float2 z[16];
    #pragma unroll
    for (int e = 0; e < 16; e++) {
        int j = tid + e * TPB;
        __half2 mm = mr[j >> 1];
        float mv = (j & 1) ? __high2float(mm) : __low2float(mm);
        z[e] = make_float2(xr[j], mv);
    }
    float2 zny;
    stransform16(z, buf0, buf1, &s_zny, tid, &zny);

    const float invN = 1.0f / 4096.0f;
    float corr = -g_D[0] * invN * invN;         // -D/N^2
    float sgnc = (i & 1) ? -corr : corr;        // (-1)^i * corr
    float sgn = (tid & 1) ? -1.0f : 1.0f;       // (-1)^j
    float2* o2 = reinterpret_cast<float2*>(out);
    float2* row0 = o2 + (2 * i) * (size_t)FN;
    float2* row1 = o2 + (2 * i + 1) * (size_t)FN;
    #pragma unroll
    for (int e = 0; e < 16; e++) {
        int j = tid + e * TPB;
        float xv = __ldcg(&xr[j]);              // reload originals (L2 hit)
        __half2 mm = __ldcg(&mr[j >> 1]);
        float mv = (j & 1) ? __high2float(mm) : __low2float(mm);
        float Rx = (z[e].x - sgn * zny.y) * invN;
        float Rm = (z[e].y + sgn * zny.x) * invN;
        row0[j] = make_float2(xv, Rx);
        row1[j] = make_float2(mv, Rm + sgn * sgnc);
    }
}

extern "C" void kernel_launch(void* const* d_in, const int* in_sizes, int n_in,
                              void* d_out, int out_size) {
    const float* x = (const float*)d_in[0];
    float* out = (float*)d_out;
    (void)in_sizes; (void)n_in; (void)out_size;

    cudaFuncSetAttribute(f1_colpass, cudaFuncAttributeMaxDynamicSharedMemorySize,
                         (int)SMEM_FFT);
    cudaFuncSetAttribute(f2_rowpass, cudaFuncAttributeMaxDynamicSharedMemorySize,
                         (int)SMEM_FFT);

    t1_transpose<<<dim3(NPAIR / 32, FN / 32), dim3(32, 8)>>>(x);
    f1_colpass<<<NPAIR, TPB, SMEM_FFT>>>();
    t2_transpose<<<dim3(FN / 32, NPAIR / 32), dim3(32, 8)>>>();
    f2_rowpass<<<FN, TPB, SMEM_FFT>>>(x, out);
}

// round 16
// speedup vs baseline: 1.0797x; 1.0797x over previous
#include <cuda_runtime.h>
#include <cuda_fp16.h>
#include <cuda_bf16.h>

// FFT-based 2x upsample, fully-real polyphase formulation (see R2/R3/R5/R12).
// R16 = R13 (best, 153.7us) + packed-f32x2 complex MULTIPLIES for variable
// twiddles: the FMA pipe (rt_SMSP=2 -> caps at 50% issue; measured 47.8% =
// saturated) sheds 2 of each cmul's 4 FFMAs into packed ops, with the pair-
// building MOVs going to the idle ALU pipe (8.9%). bfly16's constant cmuls
// stay scalar (FFMA-imm is already double-rate). + __stcs on the 256MB
// output stream. R14/R15 occupancy experiments reverted (2 CTAs were already
// resident; the FMA pipe was the real wall).

#define FN    4096
#define TPB   256
#define NPAIR (FN / 2)
#define SMEM_FFT (2 * FN * sizeof(float2))   // 64 KB double-buffer

__device__ __align__(16) __half2 g_xp [(size_t)NPAIR * FN];  // [jp][i]
__device__ __align__(16) __half2 g_M1T[(size_t)NPAIR * FN];  // [jp][i]
__device__ __align__(16) __half2 g_M1 [(size_t)FN * NPAIR];  // [i][jp]
__device__ float g_Dpart[NPAIR];
__device__ float g_D[1];
// twA[k] = e^{-2 pi i k/4096}, twB[k] = e^{+i pi k/4096}, k < 512
__device__ __align__(16) float2 g_twA[512];
__device__ __align__(16) float2 g_twB[512];

__device__ __forceinline__ float2 cmul(float2 a, float2 b) {
    return make_float2(fmaf(a.x, b.x, -a.y * b.y), fmaf(a.x, b.y, a.y * b.x));
}

// Packed complex multiply a*w (variable w): 1 mul.f32x2 + 1 fma.f32x2 on the
// FMA pipe; pair-building movs land on the ALU pipe.
//   t = {a.x,a.x} * {w.x,w.y};  r = {a.y,a.y} * {-w.y,w.x} + t
__device__ __forceinline__ float2 cmulp(float2 a, float2 w) {
    float2 r;
    float nwy = -w.y;
    asm("{\n\t.reg .b64 rax, rw, rt, ray, rwb, rr;\n\t"
        "mov.b64 rax, {%2, %2};\n\t"
        "mov.b64 rw,  {%4, %5};\n\t"
        "mul.rn.f32x2 rt, rax, rw;\n\t"
        "mov.b64 ray, {%3, %3};\n\t"
        "mov.b64 rwb, {%6, %4};\n\t"
        "fma.rn.f32x2 rr, ray, rwb, rt;\n\t"
        "mov.b64 {%0, %1}, rr;\n\t}"
        : "=f"(r.x), "=f"(r.y)
        : "f"(a.x), "f"(a.y), "f"(w.x), "f"(w.y), "f"(nwy));
    return r;
}

// Packed fp32 complex add/sub (R10): one f32x2 instruction each.
__device__ __forceinline__ float2 cadd(float2 a, float2 b) {
    float2 r;
    asm("{\n\t.reg .b64 ra, rb, rc;\n\t"
        "mov.b64 ra, {%2, %3};\n\t"
        "mov.b64 rb, {%4, %5};\n\t"
        "add.rn.f32x2 rc, ra, rb;\n\t"
        "mov.b64 {%0, %1}, rc;\n\t}"
        : "=f"(r.x), "=f"(r.y)
        : "f"(a.x), "f"(a.y), "f"(b.x), "f"(b.y));
    return r;
}
__device__ __forceinline__ float2 csub(float2 a, float2 b) {
    float2 r;
    asm("{\n\t.reg .b64 ra, rb, rc;\n\t"
        "mov.b64 ra, {%2, %3};\n\t"
        "mov.b64 rb, {%4, %5};\n\t"
        "sub.rn.f32x2 rc, ra, rb;\n\t"
        "mov.b64 {%0, %1}, rc;\n\t}"
        : "=f"(r.x), "=f"(r.y)
        : "f"(a.x), "f"(a.y), "f"(b.x), "f"(b.y));
    return r;
}

// 16-point DFT as 4x4 radix-4 (see R11). Constant cmuls stay scalar (FFMA-imm).
template <bool INV>
__device__ __forceinline__ void bfly16(const float2 x[16], float2 y[16]) {
    float2 v[16];
    #pragma unroll
    for (int j0 = 0; j0 < 4; j0++) {
        float2 p0 = x[j0], p1 = x[j0 + 4], p2 = x[j0 + 8], p3 = x[j0 + 12];
        float2 s02 = cadd(p0, p2), d02 = csub(p0, p2);
        float2 s13 = cadd(p1, p3), d13 = csub(p1, p3);
        float2 id13 = INV ? make_float2(-d13.y, d13.x) : make_float2(d13.y, -d13.x);
        v[4 * j0 + 0] = cadd(s02, s13);
        v[4 * j0 + 1] = cadd(d02, id13);
        v[4 * j0 + 2] = csub(s02, s13);
        v[4 * j0 + 3] = csub(d02, id13);
    }
    const float C1 = 0.92387953251128675613f, S1 = 0.38268343236508977173f;
    const float C2 = 0.70710678118654752440f;
    const float sg = INV ? 1.0f : -1.0f;
    const float2 W1 = make_float2(C1, sg * S1);
    const float2 W2 = make_float2(C2, sg * C2);
    const float2 W3 = make_float2(S1, sg * C1);
    const float2 W6 = make_float2(-C2, sg * C2);
    const float2 W9 = make_float2(-C1, -sg * S1);
    v[5]  = cmul(v[5],  W1);
    v[6]  = cmul(v[6],  W2);
    v[7]  = cmul(v[7],  W3);
    v[9]  = cmul(v[9],  W2);
    v[10] = INV ? make_float2(-v[10].y, v[10].x) : make_float2(v[10].y, -v[10].x);
    v[11] = cmul(v[11], W6);
    v[13] = cmul(v[13], W3);
    v[14] = cmul(v[14], W6);
    v[15] = cmul(v[15], W9);
    #pragma unroll
    for (int a0 = 0; a0 < 4; a0++) {
        float2 p0 = v[a0], p1 = v[4 + a0], p2 = v[8 + a0], p3 = v[12 + a0];
        float2 s02 = cadd(p0, p2), d02 = csub(p0, p2);
        float2 s13 = cadd(p1, p3), d13 = csub(p1, p3);
        float2 id13 = INV ? make_float2(-d13.y, d13.x) : make_float2(d13.y, -d13.x);
        y[a0]      = cadd(s02, s13);
        y[a0 + 4]  = cadd(d02, id13);
        y[a0 + 8]  = csub(s02, s13);
        y[a0 + 12] = csub(d02, id13);
    }
}

// y[k] *= w^k (k=1..15), w = base (conjugated for INV). All variable-twiddle
// multiplies use the packed cmulp.
template <bool INV>
__device__ __forceinline__ void twapply16(float2 y[16], float2 wb) {
    float2 w1 = INV ? make_float2(wb.x, -wb.y) : wb;
    float2 w2 = cmulp(w1, w1);
    float2 w3 = cmulp(w2, w1);
    float2 w4 = cmulp(w2, w2);
    float2 w5 = cmulp(w4, w1);
    float2 w6 = cmulp(w4, w2);
    float2 w7 = cmulp(w4, w3);
    float2 w8 = cmulp(w4, w4);
    y[1] = cmulp(y[1], w1); y[2] = cmulp(y[2], w2); y[3] = cmulp(y[3], w3);
    y[4] = cmulp(y[4], w4); y[5] = cmulp(y[5], w5); y[6] = cmulp(y[6], w6);
    y[7] = cmulp(y[7], w7); y[8] = cmulp(y[8], w8);
    w1 = cmulp(w1, w8); w2 = cmulp(w2, w8); w3 = cmulp(w3, w8);
    w4 = cmulp(w4, w8); w5 = cmulp(w5, w8); w6 = cmulp(w6, w8); w7 = cmulp(w7, w8);
    y[9]  = cmulp(y[9],  w1); y[10] = cmulp(y[10], w2); y[11] = cmulp(y[11], w3);
    y[12] = cmulp(y[12], w4); y[13] = cmulp(y[13], w5); y[14] = cmulp(y[14], w6);
    y[15] = cmulp(y[15], w7);
}

// S-transform (R11 structure): z[j] (= data[t + 256 j]) ->
// N * IDFT( DFT(.) * halfshift_w ), zny_out <- DFT[2048].
__device__ __forceinline__ void stransform16(float2 z[16], float2* buf0, float2* buf1,
                                             float2* s_zny, int t, float2* zny_out) {
    const int a0  = t >> 4;
    const int s4  = t & 15;
    const int m16 = a0 + 16 * s4;
    const int tSW = 16 * a0 + (s4 ^ a0);

    float2 y[16];
    const float2 w1b = __ldg(&g_twA[t]);
    const float2 w2b = __ldg(&g_twA[16 * s4]);
    const float2 wm  = __ldg(&g_twB[m16]);

    // ---- forward FFT ----
    bfly16<false>(z, y);
    twapply16<false>(y, w1b);
    #pragma unroll
    for (int a = 0; a < 16; a++) buf0[256 * a + tSW] = y[a];
    __syncthreads();
    #pragma unroll
    for (int q = 0; q < 16; q++) z[q] = buf0[256 * a0 + 16 * q + (s4 ^ q)];

    bfly16<false>(z, y);
    twapply16<false>(y, w2b);
    #pragma unroll
    for (int b = 0; b < 16; b++) buf1[256 * a0 + 16 * b + (s4 ^ b)] = y[b];
    __syncthreads();
    #pragma unroll
    for (int q = 0; q < 16; q++) z[q] = buf1[16 * t + (q ^ s4)];

    bfly16<false>(z, y);
    if (t == 0) *s_zny = y[8];                  // X[2048]

    // ---- half-sample-shift phase ----
    {
        const float2 EJ[16] = {
            { 1.0f, 0.0f},
            { 0.98078528040323044913f,  0.19509032201612826785f},
            { 0.92387953251128675613f,  0.38268343236508977173f},
            { 0.83146961230254523708f,  0.55557023301960222474f},
            { 0.70710678118654752440f,  0.70710678118654752440f},
            { 0.55557023301960222474f,  0.83146961230254523708f},
            { 0.38268343236508977173f,  0.92387953251128675613f},
            { 0.19509032201612826785f,  0.98078528040323044913f},
            { 0.0f, -1.0f},
            { 0.19509032201612826785f, -0.98078528040323044913f},
            { 0.38268343236508977173f, -0.92387953251128675613f},
            { 0.55557023301960222474f, -0.83146961230254523708f},
            { 0.70710678118654752440f, -0.70710678118654752440f},
            { 0.83146961230254523708f, -0.55557023301960222474f},
            { 0.92387953251128675613f, -0.38268343236508977173f},
            { 0.98078528040323044913f, -0.19509032201612826785f}};
        #pragma unroll
        for (int c = 0; c < 16; c++) y[c] = cmulp(y[c], cmul(wm, EJ[c]));
    }

    // ---- inverse FFT (exact mirror) ----
    bfly16<true>(y, z);
    #pragma unroll
    for (int q = 0; q < 16; q++) buf0[16 * t + (q ^ s4)] = z[q];
    __syncthreads();
    #pragma unroll
    for (int q = 0; q < 16; q++) z[q] = buf0[256 * a0 + 16 * q + (s4 ^ q)];

    twapply16<true>(z, w2b);
    bfly16<true>(z, y);
    #pragma unroll
    for (int j = 0; j < 16; j++) buf1[256 * a0 + 16 * j + (s4 ^ j)] = y[j];
    __syncthreads();
    #pragma unroll
    for (int q = 0; q < 16; q++) y[q] = buf1[256 * q + tSW];

    twapply16<true>(y, w1b);
    bfly16<true>(y, z);                         // z[j] = N*S[t + 256 j]

    *zny_out = *s_zny;                          // >= 2 syncs after the write
}

// T1: x -> xp[jp][i] = half2(x[i][2jp], x[i][2jp+1]).
// Block (0,0) additionally fills the twiddle tables (read first by F1).
__global__ void t1_transpose(const float* __restrict__ x) {
    __shared__ float2 tile[32][33];
    int tx = threadIdx.x, ty = threadIdx.y;
    int lt = ty * 32 + tx;                      // 0..255
    if (blockIdx.x == 0 && blockIdx.y == 0) {
        #pragma unroll
        for (int h = 0; h < 2; h++) {
            int k = lt + 256 * h;
            float sn, cs;
            sincospif(-(float)k / 2048.0f, &sn, &cs);
            g_twA[k] = make_float2(cs, sn);
            sincospif((float)k / 4096.0f, &sn, &cs);
            g_twB[k] = make_float2(cs, sn);
        }
    }
    const float2* xf2 = reinterpret_cast<const float2*>(x);
    int cx = blockIdx.x * 32 + tx;      // jp
    int ry = blockIdx.y * 32 + ty;      // i
    #pragma unroll
    for (int j = 0; j < 32; j += 8)
        tile[ty + j][tx] = xf2[(size_t)(ry + j) * NPAIR + cx];
    __syncthreads();
    int ox = blockIdx.y * 32 + tx;      // i
    int oy = blockIdx.x * 32 + ty;      // jp
    #pragma unroll
    for (int j = 0; j < 32; j += 8) {
        float2 v = tile[tx][ty + j];
        g_xp[(size_t)(oy + j) * FN + ox] = __floats2half2_rn(v.x, v.y);
    }
}

// F1: column pass. Block jp transforms packed x-column pair (2jp, 2jp+1).
__global__ __launch_bounds__(TPB, 2) void f1_colpass() {
    extern __shared__ float2 dsm[];
    __shared__ float2 s_zny;
    float2* buf0 = dsm;
    float2* buf1 = dsm + FN;
    int tid = threadIdx.x;
    size_t jp = blockIdx.x;
    const __half2* xp = g_xp + jp * (size_t)FN;
    float2 z[16];
    #pragma unroll
    for (int e = 0; e < 16; e++) {
        int i = tid + e * TPB;
        z[e] = __half22float2(xp[i]);
    }
    float2 zny;
    stransform16(z, buf0, buf1, &s_zny, tid, &zny);
    if (tid == 0) g_Dpart[jp] = zny.x - zny.y;

    const float invN = 1.0f / 4096.0f;
    float sgn = (tid & 1) ? -1.0f : 1.0f;       // (-1)^i
    __half2* mt = g_M1T + jp * (size_t)FN;
    #pragma unroll
    for (int e = 0; e < 16; e++) {
        int i = tid + e * TPB;
        float Ru = (z[e].x - sgn * zny.y) * invN;
        float Rv = (z[e].y + sgn * zny.x) * invN;
        mt[i] = __floats2half2_rn(Ru, Rv);
    }
}

// T2: transpose M1T -> M1. Block (0,0) additionally reduces Dpart -> D.
__global__ void t2_transpose() {
    __shared__ __half2 tile[32][33];
    __shared__ float sh[256];
    int tx = threadIdx.x, ty = threadIdx.y;
    int lt = ty * 32 + tx;                      // 0..255
    if (blockIdx.x == 0 && blockIdx.y == 0) {
        float s = 0.0f;
        #pragma unroll
        for (int h = 0; h < 8; h++) s += g_Dpart[lt + 256 * h];
        sh[lt] = s;
        __syncthreads();
        for (int o = 128; o > 0; o >>= 1) {
            if (lt < o) sh[lt] += sh[lt + o];
            __syncthreads();
        }
        if (lt == 0) g_D[0] = sh[0];
    }
    int cx = blockIdx.x * 32 + tx;      // i
    int ry = blockIdx.y * 32 + ty;      // jp
    #pragma unroll
    for (int j = 0; j < 32; j += 8)
        tile[ty + j][tx] = g_M1T[(size_t)(ry + j) * FN + cx];
    __syncthreads();
    int ox = blockIdx.y * 32 + tx;      // jp
    int oy = blockIdx.x * 32 + ty;      // i
    #pragma unroll
    for (int j = 0; j < 32; j += 8)
        g_M1[(size_t)(oy + j) * NPAIR + ox] = tile[tx][ty + j];
}

// F2: row pass. Block i packs (x row i fp32, M1 row i) as complex, transforms,
// writes output rows 2i/2i+1 directly with streaming stores (never re-read).
__global__ __launch_bounds__(TPB, 2) void f2_rowpass(const float* __restrict__ x,
                                                     float* __restrict__ out) {
    extern __shared__ float2 dsm[];
    __shared__ float2 s_zny;
    float2* buf0 = dsm;
    float2* buf1 = dsm + FN;
    int tid = threadIdx.x;
    size_t i = blockIdx.x;
    const float* xr = x + i * (size_t)FN;
    const __half2* mr = g_M1 + i * (size_t)NPAIR;
    float2 z[16], z0[16];
    #pragma unroll
    for (int e = 0; e < 16; e++) {
        int j = tid + e * TPB;
        __half2 mm = mr[j >> 1];
        float mv = (j & 1) ? __high2float(mm) : __low2float(mm);
        z[e] = make_float2(xr[j], mv);
        z0[e] = z[e];
    }
    float2 zny;
    stransform16(z, buf0, buf1, &s_zny, tid, &zny);

    const float invN = 1.0f / 4096.0f;
    float corr = -g_D[0] * invN * invN;         // -D/N^2
    float sgnc = (i & 1) ? -corr : corr;        // (-1)^i * corr
    float sgn = (tid & 1) ? -1.0f : 1.0f;       // (-1)^j
    float2* o2 = reinterpret_cast<float2*>(out);
    float2* row0 = o2 + (2 * i) * (size_t)FN;
    float2* row1 = o2 + (2 * i + 1) * (size_t)FN;
    #pragma unroll
    for (int e = 0; e < 16; e++) {
        int j = tid + e * TPB;
        float Rx = (z[e].x - sgn * zny.y) * invN;
        float Rm = (z[e].y + sgn * zny.x) * invN;
        __stcs(&row0[j], make_float2(z0[e].x, Rx));
        __stcs(&row1[j], make_float2(z0[e].y, Rm + sgn * sgnc));
    }
}

extern "C" void kernel_launch(void* const* d_in, const int* in_sizes, int n_in,
                              void* d_out, int out_size) {
    const float* x = (const float*)d_in[0];
    float* out = (float*)d_out;
    (void)in_sizes; (void)n_in; (void)out_size;

    cudaFuncSetAttribute(f1_colpass, cudaFuncAttributeMaxDynamicSharedMemorySize,
                         (int)SMEM_FFT);
    cudaFuncSetAttribute(f2_rowpass, cudaFuncAttributeMaxDynamicSharedMemorySize,
                         (int)SMEM_FFT);

    t1_transpose<<<dim3(NPAIR / 32, FN / 32), dim3(32, 8)>>>(x);
    f1_colpass<<<NPAIR, TPB, SMEM_FFT>>>();
    t2_transpose<<<dim3(FN / 32, NPAIR / 32), dim3(32, 8)>>>();
    f2_rowpass<<<FN, TPB, SMEM_FFT>>>(x, out);
}